// round 16
// baseline (speedup 1.0000x reference)
#include <cuda_runtime.h>
#include <cstdint>

// Problem constants (fixed shapes per reference)
#define N_SAMPLES 8192
#define I_BLOCK   128                 // threads per CTA
#define IPT       8                   // a-points per thread (register tile)
#define I_TILE    (I_BLOCK * IPT)     // 1024 a-points per CTA
#define K_CHUNK   32                  // b-points per CTA chunk
#define N_IBLK    (N_SAMPLES / I_TILE)    // 8
#define N_KBLK    (N_SAMPLES / K_CHUNK)   // 256
#define N_CTAS    (N_IBLK * N_KBLK)       // 2048
#define N_GATHER_CTAS (N_SAMPLES / I_BLOCK)  // 64 CTAs perform the gather

// Scratch (no allocations). All zero-init (.bss); counters are reset at the
// end of every launch so graph replays are identical.
__device__ float    g_soa[4 * N_SAMPLES]; // -2bx | -2by | -2bz | ||b||^2
__device__ float4   g_pa[N_SAMPLES];      // (ax, ay, az, ||a||^2)
__device__ unsigned g_minkey[N_SAMPLES];  // init to 0xFFFFFFFF in gather phase
__device__ unsigned g_ready;              // gather completion counter
__device__ unsigned g_done_blk[N_IBLK];   // per-i-block completion counters
__device__ float    g_psum[N_IBLK];       // per-i-block partial sums
__device__ unsigned g_done;               // global completion counter

// Packed f32x2 FMA (Blackwell FFMA2) — only reachable via PTX.
#define FMA2(d, a, b, c) \
    asm("fma.rn.f32x2 %0, %1, %2, %3;" : "=l"(d) : "l"(a), "l"(b), "l"(c))
#define PACK2(d, f) \
    asm("mov.b64 %0, {%1, %1};" : "=l"(d) : "f"(f))
#define UNPACK2(lo, hi, v) \
    asm("mov.b64 {%0, %1}, %2;" : "=f"(lo), "=f"(hi) : "l"(v))

// Monotone uint key for float (total order matches float <, incl. negatives)
__device__ __forceinline__ unsigned fkey(float f) {
    unsigned u = __float_as_uint(f);
    return (u & 0x80000000u) ? ~u : (u | 0x80000000u);
}
__device__ __forceinline__ float funkey(unsigned k) {
    unsigned u = (k & 0x80000000u) ? (k & 0x7FFFFFFFu) : ~k;
    return __uint_as_float(u);
}

// ---------------------------------------------------------------------------
// Single fused kernel. grid = (8 i-blocks, 256 k-chunks) = 2048 CTAs, 128 thr.
// Phase A (bids 0..63, wave-1 resident): gather 1 sample/thread into
//   g_soa / g_pa, init g_minkey, then bump g_ready.
// Flag barrier: every CTA's t0 polls g_ready==64 (nanosleep backoff).
// Phase B: R15 main loop (IPT=8 packed FFMA2) + hierarchical reduction.
// Last CTA writes out[0] and resets all counters for the next graph replay.
// ---------------------------------------------------------------------------
__global__ void __launch_bounds__(I_BLOCK)
chamfer_fused_kernel(const float* __restrict__ a,
                     const float* __restrict__ b,
                     const int* __restrict__ a_idx,
                     const int* __restrict__ b_idx,
                     int n_points,
                     float* __restrict__ out) {
    __shared__ float s[4 * K_CHUNK];          // 512 B, SoA b-chunk
    __shared__ float warp_sums[I_BLOCK / 32];
    __shared__ unsigned s_islast;

    const int t = threadIdx.x;
    const int bid = blockIdx.x + (int)(blockIdx.y * gridDim.x);
    const int kbase = blockIdx.y * K_CHUNK;
    const int ibase = blockIdx.x * I_TILE;

    // ---- Phase A: gather (first 64 CTAs only; one sample per thread) ----
    if (bid < N_GATHER_CTAS) {
        int i = bid * I_BLOCK + t;

        int ia = a_idx[i];
        float ax = a[ia];
        float ay = a[n_points + ia];
        float az = a[2 * n_points + ia];
        g_pa[i] = make_float4(ax, ay, az, ax * ax + ay * ay + az * az);

        int ib = b_idx[i];
        float bx = b[ib];
        float by = b[n_points + ib];
        float bz = b[2 * n_points + ib];
        g_soa[0 * N_SAMPLES + i] = -2.0f * bx;
        g_soa[1 * N_SAMPLES + i] = -2.0f * by;
        g_soa[2 * N_SAMPLES + i] = -2.0f * bz;
        g_soa[3 * N_SAMPLES + i] = bx * bx + by * by + bz * bz;

        g_minkey[i] = 0xFFFFFFFFu;   // +max key (REDG.MINs all happen post-spin)

        __threadfence();             // release stores before counter bump
        __syncthreads();
        if (t == 0) atomicAdd(&g_ready, 1u);
    }

    // ---- Flag barrier: wait until all 64 gather CTAs have published ----
    if (t == 0) {
        while (*((volatile unsigned*)&g_ready) < (unsigned)N_GATHER_CTAS)
            __nanosleep(50);
    }
    __syncthreads();   // all threads ordered after t0's observation

    // ---- Phase B: cooperative chunk load (32 float4, threads 0..31) ----
    if (t < 32) {
        int c = t >> 3;          // component (8 float4 per component)
        int j = t & 7;
        ((float4*)(s + c * K_CHUNK))[j] =
            ((const float4*)(g_soa + c * N_SAMPLES + kbase))[j];
    }

    // Load 8 a-points (coalesced: stride I_BLOCK) — overlaps with chunk load
    float4 pa[IPT];
    #pragma unroll
    for (int j = 0; j < IPT; ++j) pa[j] = g_pa[ibase + j * I_BLOCK + t];
    __syncthreads();

    unsigned long long pax2[IPT], pay2[IPT], paz2[IPT];
    #pragma unroll
    for (int j = 0; j < IPT; ++j) {
        PACK2(pax2[j], pa[j].x);
        PACK2(pay2[j], pa[j].y);
        PACK2(paz2[j], pa[j].z);
    }

    const longlong2* xs = (const longlong2*)(s);
    const longlong2* ys = (const longlong2*)(s + K_CHUNK);
    const longlong2* zs = (const longlong2*)(s + 2 * K_CHUNK);
    const longlong2* ws = (const longlong2*)(s + 3 * K_CHUNK);

    float mA[IPT], mB[IPT];
    #pragma unroll
    for (int j = 0; j < IPT; ++j) { mA[j] = 3.4e38f; mB[j] = 3.4e38f; }

    #pragma unroll 2
    for (int g = 0; g < K_CHUNK / 4; ++g) {
        longlong2 X = xs[g];   // 4 consecutive -2bx values (2 packed f32x2)
        longlong2 Y = ys[g];
        longlong2 Z = zs[g];
        longlong2 W = ws[g];

        #pragma unroll
        for (int j = 0; j < IPT; ++j) {
            unsigned long long v01, v23;
            FMA2(v01, X.x, pax2[j], W.x);
            FMA2(v23, X.y, pax2[j], W.y);
            FMA2(v01, Y.x, pay2[j], v01);
            FMA2(v23, Y.y, pay2[j], v23);
            FMA2(v01, Z.x, paz2[j], v01);
            FMA2(v23, Z.y, paz2[j], v23);

            float a0, a1, a2, a3;
            UNPACK2(a0, a1, v01);
            UNPACK2(a2, a3, v23);
            mA[j] = fminf(mA[j], fminf(a0, a1));
            mB[j] = fminf(mB[j], fminf(a2, a3));
        }
    }

    #pragma unroll
    for (int j = 0; j < IPT; ++j) {
        float m = fminf(mA[j], mB[j]);
        atomicMin(&g_minkey[ibase + j * I_BLOCK + t], fkey(m));  // -> REDG.MIN
    }

    // ---- stage 1: per-i-block completion; last k-CTA reduces its block ----
    __threadfence();
    __syncthreads();
    if (t == 0) {
        unsigned c = atomicAdd(&g_done_blk[blockIdx.x], 1u);
        s_islast = (c == (unsigned)(N_KBLK - 1)) ? 1u : 0u;
    }
    __syncthreads();
    if (!s_islast) return;

    __threadfence();  // acquire: all REDG.MIN results for this i-block visible

    float sum = 0.0f;
    #pragma unroll
    for (int j = 0; j < IPT; ++j) {
        int idx = ibase + j * I_BLOCK + t;
        unsigned kk = ((const volatile unsigned*)g_minkey)[idx];  // bypass L1
        sum += pa[j].w + funkey(kk);
    }
    // CTA reduce
    #pragma unroll
    for (int off = 16; off > 0; off >>= 1)
        sum += __shfl_down_sync(0xFFFFFFFFu, sum, off);
    if ((t & 31) == 0) warp_sums[t >> 5] = sum;
    __syncthreads();

    // ---- stage 2: global completion; last CTA's thread 0 finishes up ----
    if (t == 0) {
        g_done_blk[blockIdx.x] = 0u;   // reset own block counter for replay
        g_psum[blockIdx.x] =
            warp_sums[0] + warp_sums[1] + warp_sums[2] + warp_sums[3];
        __threadfence();
        unsigned c = atomicAdd(&g_done, 1u);
        if (c == (unsigned)(N_IBLK - 1)) {
            float total = 0.0f;
            #pragma unroll
            for (int i = 0; i < N_IBLK; ++i)
                total += ((const volatile float*)g_psum)[i];
            out[0] = total;
            // reset global counters for the next graph replay
            g_done  = 0u;
            g_ready = 0u;
        }
    }
}

// ---------------------------------------------------------------------------
extern "C" void kernel_launch(void* const* d_in, const int* in_sizes, int n_in,
                              void* d_out, int out_size) {
    const float* a     = (const float*)d_in[0];
    const float* b     = (const float*)d_in[1];
    const int*   a_idx = (const int*)d_in[2];
    const int*   b_idx = (const int*)d_in[3];
    float* out = (float*)d_out;

    int n_points = in_sizes[0] / 3;   // 16384

    chamfer_fused_kernel<<<dim3(N_IBLK, N_KBLK), I_BLOCK>>>(
        a, b, a_idx, b_idx, n_points, out);
}